// round 6
// baseline (speedup 1.0000x reference)
#include <cuda_runtime.h>
#include <cuda_bf16.h>
#include <math.h>
#include <stdint.h>

#define NTOK 16384
#define HD 768
#define FF 3072
#define NE 4

// ---------------- device scratch (no allocations allowed) ----------------
__device__ int g_counts[NE];
__device__ int g_idx[NE * NTOK];
__device__ int g_pos[NTOK];
__device__ __nv_bfloat16 g_Ahi[(size_t)NE * NTOK * HD];
__device__ __nv_bfloat16 g_Alo[(size_t)NE * NTOK * HD];
__device__ __nv_bfloat16 g_W1hi[(size_t)NE * FF * HD];   // [e][n(FF)][k(HD)]
__device__ __nv_bfloat16 g_W1lo[(size_t)NE * FF * HD];
__device__ __nv_bfloat16 g_W2hi[(size_t)NE * HD * FF];   // [e][n(HD)][k(FF)]
__device__ __nv_bfloat16 g_W2lo[(size_t)NE * HD * FF];
__device__ __nv_bfloat16 g_Hhi[(size_t)NE * NTOK * FF];
__device__ __nv_bfloat16 g_Hlo[(size_t)NE * NTOK * FF];
__device__ float g_Y[(size_t)NE * NTOK * HD];

// ---------------- small kernels ----------------
__global__ void k_zero() {
    if (threadIdx.x < NE) g_counts[threadIdx.x] = 0;
}

__global__ void k_build(const int* __restrict__ ts) {
    int t = blockIdx.x * blockDim.x + threadIdx.x;
    if (t < NTOK) {
        int e = ts[t];
        if (e > 0) {
            int s = atomicAdd(&g_counts[e - 1], 1);
            g_idx[(e - 1) * NTOK + s] = t;
            g_pos[t] = s;
        }
    }
}

__global__ void __launch_bounds__(256) k_convA(const float* __restrict__ x) {
    int e = blockIdx.y, r = blockIdx.x;
    int cnt = g_counts[e];
    int cntp = (cnt + 127) & ~127;
    if (r >= cntp) return;
    size_t ob = ((size_t)e * NTOK + r) * HD;
    if (r < cnt) {
        int tok = g_idx[e * NTOK + r];
        const float* xr = x + (size_t)tok * HD;
        for (int c = threadIdx.x; c < HD; c += 256) {
            float v = xr[c];
            __nv_bfloat16 h = __float2bfloat16(v);
            g_Ahi[ob + c] = h;
            g_Alo[ob + c] = __float2bfloat16(v - __bfloat162float(h));
        }
    } else {
        __nv_bfloat16 z = __float2bfloat16(0.f);
        for (int c = threadIdx.x; c < HD; c += 256) {
            g_Ahi[ob + c] = z;
            g_Alo[ob + c] = z;
        }
    }
}

// W1: [e][k=HD][n=FF] -> [e][n][k]
__global__ void __launch_bounds__(256) k_convW1(const float* __restrict__ W) {
    __shared__ float tile[32][33];
    int e = blockIdx.z;
    int nb = blockIdx.x * 32;
    int kb = blockIdx.y * 32;
    int tx = threadIdx.x & 31, ty = threadIdx.x >> 5;
    for (int rr = ty; rr < 32; rr += 8)
        tile[rr][tx] = W[((size_t)e * HD + kb + rr) * FF + nb + tx];
    __syncthreads();
    for (int rr = ty; rr < 32; rr += 8) {
        float v = tile[tx][rr];
        __nv_bfloat16 h = __float2bfloat16(v);
        __nv_bfloat16 l = __float2bfloat16(v - __bfloat162float(h));
        size_t o = ((size_t)e * FF + nb + rr) * HD + kb + tx;
        g_W1hi[o] = h;
        g_W1lo[o] = l;
    }
}

// W2: [e][k=FF][n=HD] -> [e][n][k]
__global__ void __launch_bounds__(256) k_convW2(const float* __restrict__ W) {
    __shared__ float tile[32][33];
    int e = blockIdx.z;
    int nb = blockIdx.x * 32;
    int kb = blockIdx.y * 32;
    int tx = threadIdx.x & 31, ty = threadIdx.x >> 5;
    for (int rr = ty; rr < 32; rr += 8)
        tile[rr][tx] = W[((size_t)e * FF + kb + rr) * HD + nb + tx];
    __syncthreads();
    for (int rr = ty; rr < 32; rr += 8) {
        float v = tile[tx][rr];
        __nv_bfloat16 h = __float2bfloat16(v);
        __nv_bfloat16 l = __float2bfloat16(v - __bfloat162float(h));
        size_t o = ((size_t)e * HD + nb + rr) * FF + kb + tx;
        g_W2hi[o] = h;
        g_W2lo[o] = l;
    }
}

// ---------------- HMMA GEMM (mma.sync bf16, bf16x3, cp.async 2-stage) ----------------
// CTA tile 128x128, BK=32, 8 warps in 4(M)x2(N): each warp 32x64.
// smem rows padded to 80B stride -> conflict-free ldmatrix.
#define RS 80
#define MAT_BYTES (128 * RS)          // 10240
#define STG_BYTES (4 * MAT_BYTES)     // 40960
#define SMEM_TOT  (2 * STG_BYTES)     // 81920

__device__ __forceinline__ uint32_t smem_u32(const void* p) {
    uint32_t a;
    asm("{ .reg .u64 t; cvta.to.shared.u64 t, %1; cvt.u32.u64 %0, t; }" : "=r"(a) : "l"(p));
    return a;
}

#define CPA16(dst, src) \
    asm volatile("cp.async.cg.shared.global [%0], [%1], 16;" :: "r"(dst), "l"(src))

#define LDM4(r0, r1, r2, r3, a)                                                  \
    asm volatile("ldmatrix.sync.aligned.m8n8.x4.shared.b16 {%0,%1,%2,%3}, [%4];" \
                 : "=r"(r0), "=r"(r1), "=r"(r2), "=r"(r3) : "r"(a))

#define MMA(d, a, b0v, b1v)                                                      \
    asm volatile("mma.sync.aligned.m16n8k16.row.col.f32.bf16.bf16.f32 "          \
                 "{%0,%1,%2,%3}, {%4,%5,%6,%7}, {%8,%9}, {%0,%1,%2,%3};"         \
                 : "+f"((d)[0]), "+f"((d)[1]), "+f"((d)[2]), "+f"((d)[3])        \
                 : "r"((a)[0]), "r"((a)[1]), "r"((a)[2]), "r"((a)[3]),           \
                   "r"(b0v), "r"(b1v))

template<int KT, int NTOT, int LAYER>
__global__ void __launch_bounds__(256, 2) k_gemm(const float* __restrict__ bias) {
    const int e = blockIdx.z;
    const int cnt = g_counts[e];
    const int row0 = blockIdx.y * 128;
    if (row0 >= cnt) return;
    const int n0 = blockIdx.x * 128;
    constexpr int C = KT / 32;
    constexpr int KU4 = KT / 8;   // uint4 per full row

    extern __shared__ __align__(16) char smem[];
    const uint32_t sb = smem_u32(smem);

    const int t = threadIdx.x;
    const int wid = t >> 5;
    const int lane = t & 31;
    const int wm = wid & 3;   // M warp: rows wm*32
    const int wn = wid >> 2;  // N warp: cols wn*64

    const __nv_bfloat16* Ah = (LAYER == 1) ? g_Ahi : g_Hhi;
    const __nv_bfloat16* Al = (LAYER == 1) ? g_Alo : g_Hlo;
    const __nv_bfloat16* Bh = (LAYER == 1) ? g_W1hi : g_W2hi;
    const __nv_bfloat16* Bl = (LAYER == 1) ? g_W1lo : g_W2lo;
    const size_t arow = (size_t)e * NTOK + row0;
    const size_t brow = (size_t)e * NTOT + n0;

    // staging: each thread copies 2 x 16B per matrix per stage
    const int r0i = t >> 2, c0i = t & 3;
    const int r1i = (t + 256) >> 2, c1i = (t + 256) & 3;
    const size_t gA0 = (arow + r0i) * (size_t)KU4 + c0i;
    const size_t gA1 = (arow + r1i) * (size_t)KU4 + c1i;
    const size_t gB0 = (brow + r0i) * (size_t)KU4 + c0i;
    const size_t gB1 = (brow + r1i) * (size_t)KU4 + c1i;
    const uint32_t s0 = (uint32_t)r0i * RS + c0i * 16;
    const uint32_t s1 = (uint32_t)r1i * RS + c1i * 16;

    auto load_stage = [&](int s, int c) {
        const uint32_t st = sb + s * STG_BYTES;
        const size_t kc = (size_t)c * 4;
        CPA16(st + 0 * MAT_BYTES + s0, (const uint4*)Ah + gA0 + kc);
        CPA16(st + 0 * MAT_BYTES + s1, (const uint4*)Ah + gA1 + kc);
        CPA16(st + 1 * MAT_BYTES + s0, (const uint4*)Al + gA0 + kc);
        CPA16(st + 1 * MAT_BYTES + s1, (const uint4*)Al + gA1 + kc);
        CPA16(st + 2 * MAT_BYTES + s0, (const uint4*)Bh + gB0 + kc);
        CPA16(st + 2 * MAT_BYTES + s1, (const uint4*)Bh + gB1 + kc);
        CPA16(st + 3 * MAT_BYTES + s0, (const uint4*)Bl + gB0 + kc);
        CPA16(st + 3 * MAT_BYTES + s1, (const uint4*)Bl + gB1 + kc);
        asm volatile("cp.async.commit_group;" ::: "memory");
    };

    // ldmatrix per-lane offsets
    const uint32_t aoff = (uint32_t)(lane & 15) * RS + (lane >> 4) * 16;
    const uint32_t boff = (uint32_t)((lane & 7) + (lane >> 4) * 8) * RS + ((lane >> 3) & 1) * 16;

    float acc[2][8][4];
    #pragma unroll
    for (int mi = 0; mi < 2; mi++)
        #pragma unroll
        for (int ni = 0; ni < 8; ni++)
            #pragma unroll
            for (int q = 0; q < 4; q++) acc[mi][ni][q] = 0.f;

    load_stage(0, 0);

    for (int c = 0; c < C; ++c) {
        if (c + 1 < C) {
            load_stage((c + 1) & 1, c + 1);
            asm volatile("cp.async.wait_group 1;" ::: "memory");
        } else {
            asm volatile("cp.async.wait_group 0;" ::: "memory");
        }
        __syncthreads();

        const uint32_t bAh = sb + (c & 1) * STG_BYTES;
        const uint32_t bAl = bAh + 1 * MAT_BYTES;
        const uint32_t bBh = bAh + 2 * MAT_BYTES;
        const uint32_t bBl = bAh + 3 * MAT_BYTES;

        #pragma unroll
        for (int ks = 0; ks < 32; ks += 16) {
            uint32_t ah[2][4], al[2][4];
            #pragma unroll
            for (int mi = 0; mi < 2; mi++) {
                uint32_t ab = (uint32_t)(wm * 32 + mi * 16) * RS + ks * 2 + aoff;
                LDM4(ah[mi][0], ah[mi][1], ah[mi][2], ah[mi][3], bAh + ab);
                LDM4(al[mi][0], al[mi][1], al[mi][2], al[mi][3], bAl + ab);
            }
            #pragma unroll
            for (int ng = 0; ng < 4; ng++) {
                uint32_t bb = (uint32_t)(wn * 64 + ng * 16) * RS + ks * 2 + boff;
                uint32_t bh[4], bl[4];
                LDM4(bh[0], bh[1], bh[2], bh[3], bBh + bb);
                LDM4(bl[0], bl[1], bl[2], bl[3], bBl + bb);
                #pragma unroll
                for (int mi = 0; mi < 2; mi++) {
                    MMA(acc[mi][ng * 2],     ah[mi], bh[0], bh[1]);
                    MMA(acc[mi][ng * 2 + 1], ah[mi], bh[2], bh[3]);
                    MMA(acc[mi][ng * 2],     al[mi], bh[0], bh[1]);
                    MMA(acc[mi][ng * 2 + 1], al[mi], bh[2], bh[3]);
                    MMA(acc[mi][ng * 2],     ah[mi], bl[0], bl[1]);
                    MMA(acc[mi][ng * 2 + 1], ah[mi], bl[2], bl[3]);
                }
            }
        }
        __syncthreads();
    }

    // ---- epilogue ----
    const int g = lane >> 2, q = lane & 3;
    #pragma unroll
    for (int mi = 0; mi < 2; mi++) {
        #pragma unroll
        for (int half = 0; half < 2; half++) {
            int r = row0 + wm * 32 + mi * 16 + g + half * 8;
            if (r >= cnt) continue;
            size_t rb = ((size_t)e * NTOK + r) * (size_t)NTOT;
            #pragma unroll
            for (int ni = 0; ni < 8; ni++) {
                int col = n0 + wn * 64 + ni * 8 + q * 2;
                float v0 = acc[mi][ni][half * 2 + 0] + bias[e * NTOT + col];
                float v1 = acc[mi][ni][half * 2 + 1] + bias[e * NTOT + col + 1];
                if (LAYER == 1) {
                    v0 = 0.5f * v0 * (1.f + erff(v0 * 0.70710678118654752f));
                    v1 = 0.5f * v1 * (1.f + erff(v1 * 0.70710678118654752f));
                    __nv_bfloat16 h0 = __float2bfloat16(v0);
                    __nv_bfloat16 h1 = __float2bfloat16(v1);
                    __nv_bfloat16 l0 = __float2bfloat16(v0 - __bfloat162float(h0));
                    __nv_bfloat16 l1 = __float2bfloat16(v1 - __bfloat162float(h1));
                    uint32_t hw = (uint32_t)__bfloat16_as_ushort(h0) |
                                  ((uint32_t)__bfloat16_as_ushort(h1) << 16);
                    uint32_t lw = (uint32_t)__bfloat16_as_ushort(l0) |
                                  ((uint32_t)__bfloat16_as_ushort(l1) << 16);
                    *(uint32_t*)(g_Hhi + rb + col) = hw;
                    *(uint32_t*)(g_Hlo + rb + col) = lw;
                } else {
                    float2 v;
                    v.x = v0; v.y = v1;
                    *(float2*)(g_Y + rb + col) = v;
                }
            }
        }
    }
}

// ---------------- LN / dispatch epilogue ----------------
__device__ __forceinline__ float2 blk_sum(float a, float b, float2* red) {
    int lane = threadIdx.x & 31;
    int w = threadIdx.x >> 5;
    #pragma unroll
    for (int o = 16; o > 0; o >>= 1) {
        a += __shfl_xor_sync(0xffffffffu, a, o);
        b += __shfl_xor_sync(0xffffffffu, b, o);
    }
    if (lane == 0) red[w] = make_float2(a, b);
    __syncthreads();
    if (w == 0) {
        float2 v = (lane < 8) ? red[lane] : make_float2(0.f, 0.f);
        a = v.x; b = v.y;
        #pragma unroll
        for (int o = 4; o > 0; o >>= 1) {
            a += __shfl_xor_sync(0xffffffffu, a, o);
            b += __shfl_xor_sync(0xffffffffu, b, o);
        }
        if (lane == 0) red[0] = make_float2(a, b);
    }
    __syncthreads();
    float2 res = red[0];
    __syncthreads();
    return res;
}

__global__ void __launch_bounds__(256) k_ln(const float* __restrict__ x,
                                            const int* __restrict__ ts,
                                            const float* __restrict__ ln_g,
                                            const float* __restrict__ ln_b,
                                            const float* __restrict__ og,
                                            const float* __restrict__ ob,
                                            float* __restrict__ out) {
    __shared__ float2 red[8];
    const int t = blockIdx.x;
    const int tid = threadIdx.x;
    const int e = ts[t];

    float xv[3], sv[3];
    #pragma unroll
    for (int k = 0; k < 3; k++) xv[k] = x[(size_t)t * HD + tid + 256 * k];

    if (e > 0) {
        const float* yr = g_Y + ((size_t)(e - 1) * NTOK + g_pos[t]) * HD;
        float yv[3];
        float s = 0.f, s2 = 0.f;
        #pragma unroll
        for (int k = 0; k < 3; k++) {
            yv[k] = yr[tid + 256 * k] + xv[k];
            s += yv[k];
            s2 += yv[k] * yv[k];
        }
        float2 r = blk_sum(s, s2, red);
        float m = r.x * (1.f / (float)HD);
        float var = r.y * (1.f / (float)HD) - m * m;
        float inv = rsqrtf(fmaxf(var, 0.f) + 1e-12f);
        #pragma unroll
        for (int k = 0; k < 3; k++) {
            int c = tid + 256 * k;
            sv[k] = (yv[k] - m) * inv * ln_g[(e - 1) * HD + c] + ln_b[(e - 1) * HD + c];
        }
    } else {
        sv[0] = sv[1] = sv[2] = 0.f;
    }

    float zv[3];
    float s = 0.f, s2 = 0.f;
    #pragma unroll
    for (int k = 0; k < 3; k++) {
        zv[k] = sv[k] + xv[k];
        s += zv[k];
        s2 += zv[k] * zv[k];
    }
    float2 r = blk_sum(s, s2, red);
    float m = r.x * (1.f / (float)HD);
    float var = r.y * (1.f / (float)HD) - m * m;
    float inv = rsqrtf(fmaxf(var, 0.f) + 1e-12f);
    #pragma unroll
    for (int k = 0; k < 3; k++) {
        int c = tid + 256 * k;
        out[(size_t)t * HD + c] = (zv[k] - m) * inv * og[c] + ob[c];
    }
}

// ---------------- launch ----------------
extern "C" void kernel_launch(void* const* d_in, const int* in_sizes, int n_in,
                              void* d_out, int out_size) {
    const float* x    = (const float*)d_in[0];
    const int*   ts   = (const int*)  d_in[1];
    const float* W1   = (const float*)d_in[2];
    const float* b1   = (const float*)d_in[3];
    const float* W2   = (const float*)d_in[4];
    const float* b2   = (const float*)d_in[5];
    const float* ln_g = (const float*)d_in[6];
    const float* ln_b = (const float*)d_in[7];
    const float* og   = (const float*)d_in[8];
    const float* ob   = (const float*)d_in[9];
    float* out = (float*)d_out;

    cudaFuncSetAttribute(k_gemm<HD, FF, 1>,
                         cudaFuncAttributeMaxDynamicSharedMemorySize, SMEM_TOT);
    cudaFuncSetAttribute(k_gemm<FF, HD, 2>,
                         cudaFuncAttributeMaxDynamicSharedMemorySize, SMEM_TOT);

    k_zero<<<1, 32>>>();
    k_build<<<NTOK / 256, 256>>>(ts);
    k_convA<<<dim3(NTOK, NE), 256>>>(x);
    k_convW1<<<dim3(FF / 32, HD / 32, NE), 256>>>(W1);
    k_convW2<<<dim3(HD / 32, FF / 32, NE), 256>>>(W2);

    k_gemm<HD, FF, 1><<<dim3(FF / 128, NTOK / 128, NE), 256, SMEM_TOT>>>(b1);
    k_gemm<FF, HD, 2><<<dim3(HD / 128, NTOK / 128, NE), 256, SMEM_TOT>>>(b2);

    k_ln<<<NTOK, 256>>>(x, ts, ln_g, ln_b, og, ob, out);
}

// round 7
// speedup vs baseline: 1.2818x; 1.2818x over previous
#include <cuda_runtime.h>
#include <cuda_fp16.h>
#include <math.h>
#include <stdint.h>

#define NTOK 16384
#define HD 768
#define FF 3072
#define NE 4

// ---------------- device scratch (no allocations allowed) ----------------
__device__ int g_counts[NE];
__device__ int g_idx[NE * NTOK];
__device__ int g_pos[NTOK];
__device__ __half g_Ahi[(size_t)NE * NTOK * HD];
__device__ __half g_Alo[(size_t)NE * NTOK * HD];
__device__ __half g_W1h[(size_t)NE * FF * HD];   // [e][n(FF)][k(HD)] fp16
__device__ __half g_W2h[(size_t)NE * HD * FF];   // [e][n(HD)][k(FF)] fp16
__device__ __half g_Hhi[(size_t)NE * NTOK * FF];
__device__ __half g_Hlo[(size_t)NE * NTOK * FF];
__device__ float g_Y[(size_t)NE * NTOK * HD];

// ---------------- small kernels ----------------
__global__ void k_zero() {
    if (threadIdx.x < NE) g_counts[threadIdx.x] = 0;
}

__global__ void k_build(const int* __restrict__ ts) {
    int t = blockIdx.x * blockDim.x + threadIdx.x;
    if (t < NTOK) {
        int e = ts[t];
        if (e > 0) {
            int s = atomicAdd(&g_counts[e - 1], 1);
            g_idx[(e - 1) * NTOK + s] = t;
            g_pos[t] = s;
        }
    }
}

__global__ void __launch_bounds__(256) k_convA(const float* __restrict__ x) {
    int e = blockIdx.y, r = blockIdx.x;
    int cnt = g_counts[e];
    int cntp = (cnt + 127) & ~127;
    if (r >= cntp) return;
    size_t ob = ((size_t)e * NTOK + r) * HD;
    if (r < cnt) {
        int tok = g_idx[e * NTOK + r];
        const float* xr = x + (size_t)tok * HD;
        for (int c = threadIdx.x; c < HD; c += 256) {
            float v = xr[c];
            __half h = __float2half(v);
            g_Ahi[ob + c] = h;
            g_Alo[ob + c] = __float2half(v - __half2float(h));
        }
    } else {
        __half z = __float2half(0.f);
        for (int c = threadIdx.x; c < HD; c += 256) {
            g_Ahi[ob + c] = z;
            g_Alo[ob + c] = z;
        }
    }
}

// W1: [e][k=HD][n=FF] -> [e][n][k] fp16
__global__ void __launch_bounds__(256) k_convW1(const float* __restrict__ W) {
    __shared__ float tile[32][33];
    int e = blockIdx.z;
    int nb = blockIdx.x * 32;
    int kb = blockIdx.y * 32;
    int tx = threadIdx.x & 31, ty = threadIdx.x >> 5;
    for (int rr = ty; rr < 32; rr += 8)
        tile[rr][tx] = W[((size_t)e * HD + kb + rr) * FF + nb + tx];
    __syncthreads();
    for (int rr = ty; rr < 32; rr += 8) {
        float v = tile[tx][rr];
        g_W1h[((size_t)e * FF + nb + rr) * HD + kb + tx] = __float2half(v);
    }
}

// W2: [e][k=FF][n=HD] -> [e][n][k] fp16
__global__ void __launch_bounds__(256) k_convW2(const float* __restrict__ W) {
    __shared__ float tile[32][33];
    int e = blockIdx.z;
    int nb = blockIdx.x * 32;
    int kb = blockIdx.y * 32;
    int tx = threadIdx.x & 31, ty = threadIdx.x >> 5;
    for (int rr = ty; rr < 32; rr += 8)
        tile[rr][tx] = W[((size_t)e * FF + kb + rr) * HD + nb + tx];
    __syncthreads();
    for (int rr = ty; rr < 32; rr += 8) {
        float v = tile[tx][rr];
        g_W2h[((size_t)e * HD + nb + rr) * FF + kb + tx] = __float2half(v);
    }
}

// ---------------- HMMA GEMM (mma.sync fp16, fp16x2 emulated fp32, cp.async) ----------------
// CTA tile 128x128, BK=32, 8 warps in 4(M)x2(N): each warp 32x64.
// smem rows padded to 80B stride -> conflict-free ldmatrix.
#define RS 80
#define MAT_BYTES (128 * RS)          // 10240
#define STG_BYTES (3 * MAT_BYTES)     // 30720
#define SMEM_TOT  (2 * STG_BYTES)     // 61440

__device__ __forceinline__ uint32_t smem_u32(const void* p) {
    uint32_t a;
    asm("{ .reg .u64 t; cvta.to.shared.u64 t, %1; cvt.u32.u64 %0, t; }" : "=r"(a) : "l"(p));
    return a;
}

#define CPA16(dst, src) \
    asm volatile("cp.async.cg.shared.global [%0], [%1], 16;" :: "r"(dst), "l"(src))

#define LDM4(r0, r1, r2, r3, a)                                                  \
    asm volatile("ldmatrix.sync.aligned.m8n8.x4.shared.b16 {%0,%1,%2,%3}, [%4];" \
                 : "=r"(r0), "=r"(r1), "=r"(r2), "=r"(r3) : "r"(a))

#define MMA(d, a, b0v, b1v)                                                      \
    asm volatile("mma.sync.aligned.m16n8k16.row.col.f32.f16.f16.f32 "            \
                 "{%0,%1,%2,%3}, {%4,%5,%6,%7}, {%8,%9}, {%0,%1,%2,%3};"         \
                 : "+f"((d)[0]), "+f"((d)[1]), "+f"((d)[2]), "+f"((d)[3])        \
                 : "r"((a)[0]), "r"((a)[1]), "r"((a)[2]), "r"((a)[3]),           \
                   "r"(b0v), "r"(b1v))

template<int KT, int NTOT, int LAYER>
__global__ void __launch_bounds__(256, 2) k_gemm(const float* __restrict__ bias) {
    const int e = blockIdx.z;
    const int cnt = g_counts[e];
    const int row0 = blockIdx.y * 128;
    if (row0 >= cnt) return;
    const int n0 = blockIdx.x * 128;
    constexpr int C = KT / 32;
    constexpr int KU4 = KT / 8;   // uint4 per full row

    extern __shared__ __align__(16) char smem[];
    const uint32_t sb = smem_u32(smem);

    const int t = threadIdx.x;
    const int wid = t >> 5;
    const int lane = t & 31;
    const int wm = wid & 3;   // M warp: rows wm*32
    const int wn = wid >> 2;  // N warp: cols wn*64

    const __half* Ah = (LAYER == 1) ? g_Ahi : g_Hhi;
    const __half* Al = (LAYER == 1) ? g_Alo : g_Hlo;
    const __half* Bh = (LAYER == 1) ? g_W1h : g_W2h;
    const size_t arow = (size_t)e * NTOK + row0;
    const size_t brow = (size_t)e * NTOT + n0;

    // staging: each thread copies 2 x 16B per matrix per stage
    const int r0i = t >> 2, c0i = t & 3;
    const int r1i = (t + 256) >> 2, c1i = (t + 256) & 3;
    const size_t gA0 = (arow + r0i) * (size_t)KU4 + c0i;
    const size_t gA1 = (arow + r1i) * (size_t)KU4 + c1i;
    const size_t gB0 = (brow + r0i) * (size_t)KU4 + c0i;
    const size_t gB1 = (brow + r1i) * (size_t)KU4 + c1i;
    const uint32_t s0 = (uint32_t)r0i * RS + c0i * 16;
    const uint32_t s1 = (uint32_t)r1i * RS + c1i * 16;

    auto load_stage = [&](int s, int c) {
        const uint32_t st = sb + s * STG_BYTES;
        const size_t kc = (size_t)c * 4;
        CPA16(st + 0 * MAT_BYTES + s0, (const uint4*)Ah + gA0 + kc);
        CPA16(st + 0 * MAT_BYTES + s1, (const uint4*)Ah + gA1 + kc);
        CPA16(st + 1 * MAT_BYTES + s0, (const uint4*)Al + gA0 + kc);
        CPA16(st + 1 * MAT_BYTES + s1, (const uint4*)Al + gA1 + kc);
        CPA16(st + 2 * MAT_BYTES + s0, (const uint4*)Bh + gB0 + kc);
        CPA16(st + 2 * MAT_BYTES + s1, (const uint4*)Bh + gB1 + kc);
        asm volatile("cp.async.commit_group;" ::: "memory");
    };

    // ldmatrix per-lane offsets
    const uint32_t aoff = (uint32_t)(lane & 15) * RS + (lane >> 4) * 16;
    const uint32_t boff = (uint32_t)((lane & 7) + (lane >> 4) * 8) * RS + ((lane >> 3) & 1) * 16;

    float acc[2][8][4];
    #pragma unroll
    for (int mi = 0; mi < 2; mi++)
        #pragma unroll
        for (int ni = 0; ni < 8; ni++)
            #pragma unroll
            for (int q = 0; q < 4; q++) acc[mi][ni][q] = 0.f;

    load_stage(0, 0);

    for (int c = 0; c < C; ++c) {
        if (c + 1 < C) {
            load_stage((c + 1) & 1, c + 1);
            asm volatile("cp.async.wait_group 1;" ::: "memory");
        } else {
            asm volatile("cp.async.wait_group 0;" ::: "memory");
        }
        __syncthreads();

        const uint32_t bAh = sb + (c & 1) * STG_BYTES;
        const uint32_t bAl = bAh + 1 * MAT_BYTES;
        const uint32_t bBh = bAh + 2 * MAT_BYTES;

        #pragma unroll
        for (int ks = 0; ks < 32; ks += 16) {
            uint32_t ah[2][4], al[2][4];
            #pragma unroll
            for (int mi = 0; mi < 2; mi++) {
                uint32_t ab = (uint32_t)(wm * 32 + mi * 16) * RS + ks * 2 + aoff;
                LDM4(ah[mi][0], ah[mi][1], ah[mi][2], ah[mi][3], bAh + ab);
                LDM4(al[mi][0], al[mi][1], al[mi][2], al[mi][3], bAl + ab);
            }
            #pragma unroll
            for (int ng = 0; ng < 4; ng++) {
                uint32_t bb = (uint32_t)(wn * 64 + ng * 16) * RS + ks * 2 + boff;
                uint32_t bh[4];
                LDM4(bh[0], bh[1], bh[2], bh[3], bBh + bb);
                #pragma unroll
                for (int mi = 0; mi < 2; mi++) {
                    MMA(acc[mi][ng * 2],     ah[mi], bh[0], bh[1]);
                    MMA(acc[mi][ng * 2 + 1], ah[mi], bh[2], bh[3]);
                    MMA(acc[mi][ng * 2],     al[mi], bh[0], bh[1]);
                    MMA(acc[mi][ng * 2 + 1], al[mi], bh[2], bh[3]);
                }
            }
        }
        __syncthreads();
    }

    // ---- epilogue ----
    const int g = lane >> 2, q = lane & 3;
    #pragma unroll
    for (int mi = 0; mi < 2; mi++) {
        #pragma unroll
        for (int half = 0; half < 2; half++) {
            int r = row0 + wm * 32 + mi * 16 + g + half * 8;
            if (r >= cnt) continue;
            size_t rb = ((size_t)e * NTOK + r) * (size_t)NTOT;
            #pragma unroll
            for (int ni = 0; ni < 8; ni++) {
                int col = n0 + wn * 64 + ni * 8 + q * 2;
                float v0 = acc[mi][ni][half * 2 + 0] + bias[e * NTOT + col];
                float v1 = acc[mi][ni][half * 2 + 1] + bias[e * NTOT + col + 1];
                if (LAYER == 1) {
                    v0 = 0.5f * v0 * (1.f + erff(v0 * 0.70710678118654752f));
                    v1 = 0.5f * v1 * (1.f + erff(v1 * 0.70710678118654752f));
                    __half h0 = __float2half(v0);
                    __half h1 = __float2half(v1);
                    __half l0 = __float2half(v0 - __half2float(h0));
                    __half l1 = __float2half(v1 - __half2float(h1));
                    uint32_t hw = (uint32_t)__half_as_ushort(h0) |
                                  ((uint32_t)__half_as_ushort(h1) << 16);
                    uint32_t lw = (uint32_t)__half_as_ushort(l0) |
                                  ((uint32_t)__half_as_ushort(l1) << 16);
                    *(uint32_t*)(g_Hhi + rb + col) = hw;
                    *(uint32_t*)(g_Hlo + rb + col) = lw;
                } else {
                    float2 v;
                    v.x = v0; v.y = v1;
                    *(float2*)(g_Y + rb + col) = v;
                }
            }
        }
    }
}

// ---------------- LN / dispatch epilogue ----------------
__device__ __forceinline__ float2 blk_sum(float a, float b, float2* red) {
    int lane = threadIdx.x & 31;
    int w = threadIdx.x >> 5;
    #pragma unroll
    for (int o = 16; o > 0; o >>= 1) {
        a += __shfl_xor_sync(0xffffffffu, a, o);
        b += __shfl_xor_sync(0xffffffffu, b, o);
    }
    if (lane == 0) red[w] = make_float2(a, b);
    __syncthreads();
    if (w == 0) {
        float2 v = (lane < 8) ? red[lane] : make_float2(0.f, 0.f);
        a = v.x; b = v.y;
        #pragma unroll
        for (int o = 4; o > 0; o >>= 1) {
            a += __shfl_xor_sync(0xffffffffu, a, o);
            b += __shfl_xor_sync(0xffffffffu, b, o);
        }
        if (lane == 0) red[0] = make_float2(a, b);
    }
    __syncthreads();
    float2 res = red[0];
    __syncthreads();
    return res;
}

__global__ void __launch_bounds__(256) k_ln(const float* __restrict__ x,
                                            const int* __restrict__ ts,
                                            const float* __restrict__ ln_g,
                                            const float* __restrict__ ln_b,
                                            const float* __restrict__ og,
                                            const float* __restrict__ ob,
                                            float* __restrict__ out) {
    __shared__ float2 red[8];
    const int t = blockIdx.x;
    const int tid = threadIdx.x;
    const int e = ts[t];

    float xv[3], sv[3];
    #pragma unroll
    for (int k = 0; k < 3; k++) xv[k] = x[(size_t)t * HD + tid + 256 * k];

    if (e > 0) {
        const float* yr = g_Y + ((size_t)(e - 1) * NTOK + g_pos[t]) * HD;
        float yv[3];
        float s = 0.f, s2 = 0.f;
        #pragma unroll
        for (int k = 0; k < 3; k++) {
            yv[k] = yr[tid + 256 * k] + xv[k];
            s += yv[k];
            s2 += yv[k] * yv[k];
        }
        float2 r = blk_sum(s, s2, red);
        float m = r.x * (1.f / (float)HD);
        float var = r.y * (1.f / (float)HD) - m * m;
        float inv = rsqrtf(fmaxf(var, 0.f) + 1e-12f);
        #pragma unroll
        for (int k = 0; k < 3; k++) {
            int c = tid + 256 * k;
            sv[k] = (yv[k] - m) * inv * ln_g[(e - 1) * HD + c] + ln_b[(e - 1) * HD + c];
        }
    } else {
        sv[0] = sv[1] = sv[2] = 0.f;
    }

    float zv[3];
    float s = 0.f, s2 = 0.f;
    #pragma unroll
    for (int k = 0; k < 3; k++) {
        zv[k] = sv[k] + xv[k];
        s += zv[k];
        s2 += zv[k] * zv[k];
    }
    float2 r = blk_sum(s, s2, red);
    float m = r.x * (1.f / (float)HD);
    float var = r.y * (1.f / (float)HD) - m * m;
    float inv = rsqrtf(fmaxf(var, 0.f) + 1e-12f);
    #pragma unroll
    for (int k = 0; k < 3; k++) {
        int c = tid + 256 * k;
        out[(size_t)t * HD + c] = (zv[k] - m) * inv * og[c] + ob[c];
    }
}

// ---------------- launch ----------------
extern "C" void kernel_launch(void* const* d_in, const int* in_sizes, int n_in,
                              void* d_out, int out_size) {
    const float* x    = (const float*)d_in[0];
    const int*   ts   = (const int*)  d_in[1];
    const float* W1   = (const float*)d_in[2];
    const float* b1   = (const float*)d_in[3];
    const float* W2   = (const float*)d_in[4];
    const float* b2   = (const float*)d_in[5];
    const float* ln_g = (const float*)d_in[6];
    const float* ln_b = (const float*)d_in[7];
    const float* og   = (const float*)d_in[8];
    const float* ob   = (const float*)d_in[9];
    float* out = (float*)d_out;

    cudaFuncSetAttribute(k_gemm<HD, FF, 1>,
                         cudaFuncAttributeMaxDynamicSharedMemorySize, SMEM_TOT);
    cudaFuncSetAttribute(k_gemm<FF, HD, 2>,
                         cudaFuncAttributeMaxDynamicSharedMemorySize, SMEM_TOT);

    k_zero<<<1, 32>>>();
    k_build<<<NTOK / 256, 256>>>(ts);
    k_convA<<<dim3(NTOK, NE), 256>>>(x);
    k_convW1<<<dim3(FF / 32, HD / 32, NE), 256>>>(W1);
    k_convW2<<<dim3(HD / 32, FF / 32, NE), 256>>>(W2);

    k_gemm<HD, FF, 1><<<dim3(FF / 128, NTOK / 128, NE), 256, SMEM_TOT>>>(b1);
    k_gemm<FF, HD, 2><<<dim3(HD / 128, NTOK / 128, NE), 256, SMEM_TOT>>>(b2);

    k_ln<<<NTOK, 256>>>(x, ts, ln_g, ln_b, og, ob, out);
}

// round 8
// speedup vs baseline: 2.0087x; 1.5672x over previous
#include <cuda_runtime.h>
#include <cuda_fp16.h>
#include <math.h>
#include <stdint.h>

#define NTOK 16384
#define HD 768
#define FF 3072
#define NE 4

// ---------------- device scratch (no allocations allowed) ----------------
__device__ int g_counts[NE];
__device__ int g_idx[NE * NTOK];
__device__ int g_pos[NTOK];
__device__ __half g_Ah[(size_t)NE * NTOK * HD];
__device__ __half g_W1h[(size_t)NE * FF * HD];   // [e][n(FF)][k(HD)] fp16
__device__ __half g_W2h[(size_t)NE * HD * FF];   // [e][n(HD)][k(FF)] fp16
__device__ __half g_Hh[(size_t)NE * NTOK * FF];
__device__ float g_Y[(size_t)NE * NTOK * HD];

// ---------------- small kernels ----------------
__global__ void k_zero() {
    if (threadIdx.x < NE) g_counts[threadIdx.x] = 0;
}

__global__ void k_build(const int* __restrict__ ts) {
    int t = blockIdx.x * blockDim.x + threadIdx.x;
    if (t < NTOK) {
        int e = ts[t];
        if (e > 0) {
            int s = atomicAdd(&g_counts[e - 1], 1);
            g_idx[(e - 1) * NTOK + s] = t;
            g_pos[t] = s;
        }
    }
}

__global__ void __launch_bounds__(256) k_convA(const float* __restrict__ x) {
    int e = blockIdx.y, r = blockIdx.x;
    int cnt = g_counts[e];
    int cntp = (cnt + 127) & ~127;
    if (r >= cntp) return;
    size_t ob = ((size_t)e * NTOK + r) * HD;
    if (r < cnt) {
        int tok = g_idx[e * NTOK + r];
        const float* xr = x + (size_t)tok * HD;
        for (int c = threadIdx.x; c < HD; c += 256)
            g_Ah[ob + c] = __float2half(xr[c]);
    } else {
        __half z = __float2half(0.f);
        for (int c = threadIdx.x; c < HD; c += 256)
            g_Ah[ob + c] = z;
    }
}

// W1: [e][k=HD][n=FF] -> [e][n][k] fp16
__global__ void __launch_bounds__(256) k_convW1(const float* __restrict__ W) {
    __shared__ float tile[32][33];
    int e = blockIdx.z;
    int nb = blockIdx.x * 32;
    int kb = blockIdx.y * 32;
    int tx = threadIdx.x & 31, ty = threadIdx.x >> 5;
    for (int rr = ty; rr < 32; rr += 8)
        tile[rr][tx] = W[((size_t)e * HD + kb + rr) * FF + nb + tx];
    __syncthreads();
    for (int rr = ty; rr < 32; rr += 8)
        g_W1h[((size_t)e * FF + nb + rr) * HD + kb + tx] = __float2half(tile[tx][rr]);
}

// W2: [e][k=FF][n=HD] -> [e][n][k] fp16
__global__ void __launch_bounds__(256) k_convW2(const float* __restrict__ W) {
    __shared__ float tile[32][33];
    int e = blockIdx.z;
    int nb = blockIdx.x * 32;
    int kb = blockIdx.y * 32;
    int tx = threadIdx.x & 31, ty = threadIdx.x >> 5;
    for (int rr = ty; rr < 32; rr += 8)
        tile[rr][tx] = W[((size_t)e * FF + kb + rr) * HD + nb + tx];
    __syncthreads();
    for (int rr = ty; rr < 32; rr += 8)
        g_W2h[((size_t)e * HD + nb + rr) * FF + kb + tx] = __float2half(tile[tx][rr]);
}

// ---------------- HMMA GEMM (mma.sync fp16, cp.async 2-stage) ----------------
// CTA tile 128x128, BK=32, 8 warps in 4(M)x2(N): each warp 32x64.
// smem rows padded to 80B stride -> conflict-free ldmatrix.
#define RS 80
#define MAT_BYTES (128 * RS)          // 10240
#define STG_BYTES (2 * MAT_BYTES)     // 20480
#define SMEM_TOT  (2 * STG_BYTES)     // 40960

__device__ __forceinline__ uint32_t smem_u32(const void* p) {
    uint32_t a;
    asm("{ .reg .u64 t; cvta.to.shared.u64 t, %1; cvt.u32.u64 %0, t; }" : "=r"(a) : "l"(p));
    return a;
}

#define CPA16(dst, src) \
    asm volatile("cp.async.cg.shared.global [%0], [%1], 16;" :: "r"(dst), "l"(src))

#define LDM4(r0, r1, r2, r3, a)                                                  \
    asm volatile("ldmatrix.sync.aligned.m8n8.x4.shared.b16 {%0,%1,%2,%3}, [%4];" \
                 : "=r"(r0), "=r"(r1), "=r"(r2), "=r"(r3) : "r"(a))

#define MMA(d, a, b0v, b1v)                                                      \
    asm volatile("mma.sync.aligned.m16n8k16.row.col.f32.f16.f16.f32 "            \
                 "{%0,%1,%2,%3}, {%4,%5,%6,%7}, {%8,%9}, {%0,%1,%2,%3};"         \
                 : "+f"((d)[0]), "+f"((d)[1]), "+f"((d)[2]), "+f"((d)[3])        \
                 : "r"((a)[0]), "r"((a)[1]), "r"((a)[2]), "r"((a)[3]),           \
                   "r"(b0v), "r"(b1v))

template<int KT, int NTOT, int LAYER>
__global__ void __launch_bounds__(256, 2) k_gemm(const float* __restrict__ bias) {
    const int e = blockIdx.z;
    const int cnt = g_counts[e];
    const int row0 = blockIdx.y * 128;
    if (row0 >= cnt) return;
    const int n0 = blockIdx.x * 128;
    constexpr int C = KT / 32;
    constexpr int KU4 = KT / 8;   // uint4 per full row

    extern __shared__ __align__(16) char smem[];
    const uint32_t sb = smem_u32(smem);

    const int t = threadIdx.x;
    const int wid = t >> 5;
    const int lane = t & 31;
    const int wm = wid & 3;   // M warp: rows wm*32
    const int wn = wid >> 2;  // N warp: cols wn*64

    const __half* Ah = (LAYER == 1) ? g_Ah : g_Hh;
    const __half* Bh = (LAYER == 1) ? g_W1h : g_W2h;
    const size_t arow = (size_t)e * NTOK + row0;
    const size_t brow = (size_t)e * NTOT + n0;

    // staging: each thread copies 2 x 16B per matrix per stage
    const int r0i = t >> 2, c0i = t & 3;
    const int r1i = (t + 256) >> 2, c1i = (t + 256) & 3;
    const size_t gA0 = (arow + r0i) * (size_t)KU4 + c0i;
    const size_t gA1 = (arow + r1i) * (size_t)KU4 + c1i;
    const size_t gB0 = (brow + r0i) * (size_t)KU4 + c0i;
    const size_t gB1 = (brow + r1i) * (size_t)KU4 + c1i;
    const uint32_t s0 = (uint32_t)r0i * RS + c0i * 16;
    const uint32_t s1 = (uint32_t)r1i * RS + c1i * 16;

    auto load_stage = [&](int s, int c) {
        const uint32_t st = sb + s * STG_BYTES;
        const size_t kc = (size_t)c * 4;
        CPA16(st + 0 * MAT_BYTES + s0, (const uint4*)Ah + gA0 + kc);
        CPA16(st + 0 * MAT_BYTES + s1, (const uint4*)Ah + gA1 + kc);
        CPA16(st + 1 * MAT_BYTES + s0, (const uint4*)Bh + gB0 + kc);
        CPA16(st + 1 * MAT_BYTES + s1, (const uint4*)Bh + gB1 + kc);
        asm volatile("cp.async.commit_group;" ::: "memory");
    };

    // ldmatrix per-lane offsets
    const uint32_t aoff = (uint32_t)(lane & 15) * RS + (lane >> 4) * 16;
    const uint32_t boff = (uint32_t)((lane & 7) + (lane >> 4) * 8) * RS + ((lane >> 3) & 1) * 16;

    float acc[2][8][4];
    #pragma unroll
    for (int mi = 0; mi < 2; mi++)
        #pragma unroll
        for (int ni = 0; ni < 8; ni++)
            #pragma unroll
            for (int q = 0; q < 4; q++) acc[mi][ni][q] = 0.f;

    load_stage(0, 0);

    for (int c = 0; c < C; ++c) {
        if (c + 1 < C) {
            load_stage((c + 1) & 1, c + 1);
            asm volatile("cp.async.wait_group 1;" ::: "memory");
        } else {
            asm volatile("cp.async.wait_group 0;" ::: "memory");
        }
        __syncthreads();

        const uint32_t bAh = sb + (c & 1) * STG_BYTES;
        const uint32_t bBh = bAh + 1 * MAT_BYTES;

        #pragma unroll
        for (int ks = 0; ks < 32; ks += 16) {
            uint32_t ah[2][4];
            #pragma unroll
            for (int mi = 0; mi < 2; mi++) {
                uint32_t ab = (uint32_t)(wm * 32 + mi * 16) * RS + ks * 2 + aoff;
                LDM4(ah[mi][0], ah[mi][1], ah[mi][2], ah[mi][3], bAh + ab);
            }
            #pragma unroll
            for (int ng = 0; ng < 4; ng++) {
                uint32_t bb = (uint32_t)(wn * 64 + ng * 16) * RS + ks * 2 + boff;
                uint32_t bh[4];
                LDM4(bh[0], bh[1], bh[2], bh[3], bBh + bb);
                #pragma unroll
                for (int mi = 0; mi < 2; mi++) {
                    MMA(acc[mi][ng * 2],     ah[mi], bh[0], bh[1]);
                    MMA(acc[mi][ng * 2 + 1], ah[mi], bh[2], bh[3]);
                }
            }
        }
        __syncthreads();
    }

    // ---- epilogue ----
    const int g = lane >> 2, q = lane & 3;
    #pragma unroll
    for (int mi = 0; mi < 2; mi++) {
        #pragma unroll
        for (int half = 0; half < 2; half++) {
            int r = row0 + wm * 32 + mi * 16 + g + half * 8;
            if (r >= cnt) continue;
            size_t rb = ((size_t)e * NTOK + r) * (size_t)NTOT;
            #pragma unroll
            for (int ni = 0; ni < 8; ni++) {
                int col = n0 + wn * 64 + ni * 8 + q * 2;
                float v0 = acc[mi][ni][half * 2 + 0] + bias[e * NTOT + col];
                float v1 = acc[mi][ni][half * 2 + 1] + bias[e * NTOT + col + 1];
                if (LAYER == 1) {
                    v0 = 0.5f * v0 * (1.f + erff(v0 * 0.70710678118654752f));
                    v1 = 0.5f * v1 * (1.f + erff(v1 * 0.70710678118654752f));
                    __half h0 = __float2half(v0);
                    __half h1 = __float2half(v1);
                    uint32_t hw = (uint32_t)__half_as_ushort(h0) |
                                  ((uint32_t)__half_as_ushort(h1) << 16);
                    *(uint32_t*)(g_Hh + rb + col) = hw;
                } else {
                    float2 v;
                    v.x = v0; v.y = v1;
                    *(float2*)(g_Y + rb + col) = v;
                }
            }
        }
    }
}

// ---------------- LN / dispatch epilogue ----------------
__device__ __forceinline__ float2 blk_sum(float a, float b, float2* red) {
    int lane = threadIdx.x & 31;
    int w = threadIdx.x >> 5;
    #pragma unroll
    for (int o = 16; o > 0; o >>= 1) {
        a += __shfl_xor_sync(0xffffffffu, a, o);
        b += __shfl_xor_sync(0xffffffffu, b, o);
    }
    if (lane == 0) red[w] = make_float2(a, b);
    __syncthreads();
    if (w == 0) {
        float2 v = (lane < 8) ? red[lane] : make_float2(0.f, 0.f);
        a = v.x; b = v.y;
        #pragma unroll
        for (int o = 4; o > 0; o >>= 1) {
            a += __shfl_xor_sync(0xffffffffu, a, o);
            b += __shfl_xor_sync(0xffffffffu, b, o);
        }
        if (lane == 0) red[0] = make_float2(a, b);
    }
    __syncthreads();
    float2 res = red[0];
    __syncthreads();
    return res;
}

__global__ void __launch_bounds__(256) k_ln(const float* __restrict__ x,
                                            const int* __restrict__ ts,
                                            const float* __restrict__ ln_g,
                                            const float* __restrict__ ln_b,
                                            const float* __restrict__ og,
                                            const float* __restrict__ ob,
                                            float* __restrict__ out) {
    __shared__ float2 red[8];
    const int t = blockIdx.x;
    const int tid = threadIdx.x;
    const int e = ts[t];

    float xv[3], sv[3];
    #pragma unroll
    for (int k = 0; k < 3; k++) xv[k] = x[(size_t)t * HD + tid + 256 * k];

    if (e > 0) {
        const float* yr = g_Y + ((size_t)(e - 1) * NTOK + g_pos[t]) * HD;
        float yv[3];
        float s = 0.f, s2 = 0.f;
        #pragma unroll
        for (int k = 0; k < 3; k++) {
            yv[k] = yr[tid + 256 * k] + xv[k];
            s += yv[k];
            s2 += yv[k] * yv[k];
        }
        float2 r = blk_sum(s, s2, red);
        float m = r.x * (1.f / (float)HD);
        float var = r.y * (1.f / (float)HD) - m * m;
        float inv = rsqrtf(fmaxf(var, 0.f) + 1e-12f);
        #pragma unroll
        for (int k = 0; k < 3; k++) {
            int c = tid + 256 * k;
            sv[k] = (yv[k] - m) * inv * ln_g[(e - 1) * HD + c] + ln_b[(e - 1) * HD + c];
        }
    } else {
        sv[0] = sv[1] = sv[2] = 0.f;
    }

    float zv[3];
    float s = 0.f, s2 = 0.f;
    #pragma unroll
    for (int k = 0; k < 3; k++) {
        zv[k] = sv[k] + xv[k];
        s += zv[k];
        s2 += zv[k] * zv[k];
    }
    float2 r = blk_sum(s, s2, red);
    float m = r.x * (1.f / (float)HD);
    float var = r.y * (1.f / (float)HD) - m * m;
    float inv = rsqrtf(fmaxf(var, 0.f) + 1e-12f);
    #pragma unroll
    for (int k = 0; k < 3; k++) {
        int c = tid + 256 * k;
        out[(size_t)t * HD + c] = (zv[k] - m) * inv * og[c] + ob[c];
    }
}

// ---------------- launch ----------------
extern "C" void kernel_launch(void* const* d_in, const int* in_sizes, int n_in,
                              void* d_out, int out_size) {
    const float* x    = (const float*)d_in[0];
    const int*   ts   = (const int*)  d_in[1];
    const float* W1   = (const float*)d_in[2];
    const float* b1   = (const float*)d_in[3];
    const float* W2   = (const float*)d_in[4];
    const float* b2   = (const float*)d_in[5];
    const float* ln_g = (const float*)d_in[6];
    const float* ln_b = (const float*)d_in[7];
    const float* og   = (const float*)d_in[8];
    const float* ob   = (const float*)d_in[9];
    float* out = (float*)d_out;

    cudaFuncSetAttribute(k_gemm<HD, FF, 1>,
                         cudaFuncAttributeMaxDynamicSharedMemorySize, SMEM_TOT);
    cudaFuncSetAttribute(k_gemm<FF, HD, 2>,
                         cudaFuncAttributeMaxDynamicSharedMemorySize, SMEM_TOT);

    k_zero<<<1, 32>>>();
    k_build<<<NTOK / 256, 256>>>(ts);
    k_convA<<<dim3(NTOK, NE), 256>>>(x);
    k_convW1<<<dim3(FF / 32, HD / 32, NE), 256>>>(W1);
    k_convW2<<<dim3(HD / 32, FF / 32, NE), 256>>>(W2);

    k_gemm<HD, FF, 1><<<dim3(FF / 128, NTOK / 128, NE), 256, SMEM_TOT>>>(b1);
    k_gemm<FF, HD, 2><<<dim3(HD / 128, NTOK / 128, NE), 256, SMEM_TOT>>>(b2);

    k_ln<<<NTOK, 256>>>(x, ts, ln_g, ln_b, og, ob, out);
}